// round 5
// baseline (speedup 1.0000x reference)
#include <cuda_runtime.h>

#define T_LEN 65536
#define H     128

// Scratch: per-timestep hidden states for both directions.
__device__ float g_hf[T_LEN * H];
__device__ float g_hb[T_LEN * H];
__device__ unsigned g_maskw[T_LEN / 32];

// Fast approx math (MUFU only, no IEEE div sequences).
__device__ __forceinline__ float ex2a(float x) {
    float y; asm("ex2.approx.f32 %0, %1;" : "=f"(y) : "f"(x)); return y;
}
__device__ __forceinline__ float rcpa(float x) {
    float y; asm("rcp.approx.f32 %0, %1;" : "=f"(y) : "f"(x)); return y;
}
#define LOG2E 1.4426950408889634f
__device__ __forceinline__ float sigmoid_fast(float x) {
    return rcpa(1.0f + ex2a(-x * LOG2E));
}
__device__ __forceinline__ float tanh_fast(float x) {
    float ax = fabsf(x);
    float e  = ex2a(ax * (-2.0f * LOG2E));
    float t  = (1.0f - e) * rcpa(1.0f + e);
    return copysignf(t, x);
}

// Packed f32x2 FMA (2 MACs/instr) — only reachable via inline PTX on sm_103a.
__device__ __forceinline__ unsigned long long fma2(unsigned long long a,
                                                   unsigned long long b,
                                                   unsigned long long c) {
    unsigned long long d;
    asm("fma.rn.f32x2 %0, %1, %2, %3;" : "=l"(d) : "l"(a), "l"(b), "l"(c));
    return d;
}
__device__ __forceinline__ float hsum2(unsigned long long a, unsigned long long b) {
    unsigned long long s;
    asm("add.rn.f32x2 %0, %1, %2;" : "=l"(s) : "l"(a), "l"(b));
    float2 f = *reinterpret_cast<float2*>(&s);
    return f.x + f.y;
}

// ---------------------------------------------------------------------------
// GRU kernel: grid = 2 (dir), 512 threads = 128 units x 4 quarter-threads.
// Thread (unit, q) owns 32 cols of gate rows r,z,n of `unit` in interleaved
// 16B granules (indices q, q+4, ..., q+28) -> conflict-free LDS.128 of h.
// 48 u64 weight regs; 2-level shfl_xor reduce; async-proxy store ring
// (bar.sync does NOT drain cp.async.bulk); ONE __syncthreads per step.
// ---------------------------------------------------------------------------
__global__ void __launch_bounds__(512, 1) gru_kernel(
    const float* __restrict__ signal,
    const float* __restrict__ Wih_f, const float* __restrict__ Whh_f,
    const float* __restrict__ bih_f, const float* __restrict__ bhh_f,
    const float* __restrict__ Wih_b, const float* __restrict__ Whh_b,
    const float* __restrict__ bih_b, const float* __restrict__ bhh_b)
{
    const int dir = blockIdx.x;
    const float* __restrict__ Wih = dir ? Wih_b : Wih_f;
    const float* __restrict__ Whh = dir ? Whh_b : Whh_f;
    const float* __restrict__ bih = dir ? bih_b : bih_f;
    const float* __restrict__ bhh = dir ? bhh_b : bhh_f;
    float* __restrict__ hout = dir ? g_hb : g_hf;

    const int tid  = threadIdx.x;
    const int unit = tid >> 2;   // 0..127
    const int q    = tid & 3;    // 0..3

    __shared__ __align__(16) float h_sh[2][H];
    __shared__ __align__(16) float ring[2][32][H];   // 32 KB
    __shared__ float sig_sh[4096];                    // 16 KB

    const int row_r = unit;
    const int row_z = H + unit;
    const int row_n = 2 * H + unit;

    // Register-resident weights: 8 granules (16B each) per gate per thread.
    unsigned long long wr[16], wz[16], wn[16];
    #pragma unroll
    for (int k = 0; k < 8; k++) {
        const int g = q + 4 * k;       // granule index 0..31
        const unsigned long long* pr =
            reinterpret_cast<const unsigned long long*>(Whh + row_r * H + 4 * g);
        const unsigned long long* pz =
            reinterpret_cast<const unsigned long long*>(Whh + row_z * H + 4 * g);
        const unsigned long long* pn =
            reinterpret_cast<const unsigned long long*>(Whh + row_n * H + 4 * g);
        wr[2 * k] = pr[0]; wr[2 * k + 1] = pr[1];
        wz[2 * k] = pz[0]; wz[2 * k + 1] = pz[1];
        wn[2 * k] = pn[0]; wn[2 * k + 1] = pn[1];
    }
    const float wih_r = Wih[row_r], wih_z = Wih[row_z], wih_n = Wih[row_n];
    // Fold biases: r,z use (bih+bhh); n needs them separate.
    const float br  = bih[row_r] + bhh[row_r];
    const float bz  = bih[row_z] + bhh[row_z];
    const float bin = bih[row_n];
    const float bhn = bhh[row_n];

    float hcur = 0.0f;
    if (tid < H) h_sh[0][tid] = 0.0f;
    __syncthreads();

    for (int t = 0; t < T_LEN; t++) {
        if ((t & 4095) == 0) {
            // previous step ended with __syncthreads -> safe to refill
            for (int k = tid; k < 4096; k += 512) {
                const int idx = t + k;
                sig_sh[k] = dir ? signal[T_LEN - 1 - idx] : signal[idx];
            }
            __syncthreads();
        }

        const float x = sig_sh[t & 4095];

        const ulonglong2* h4 = reinterpret_cast<const ulonglong2*>(h_sh[t & 1]);
        unsigned long long ar0 = 0ULL, ar1 = 0ULL;
        unsigned long long az0 = 0ULL, az1 = 0ULL;
        unsigned long long an0 = 0ULL, an1 = 0ULL;
        #pragma unroll
        for (int k = 0; k < 8; k++) {
            const ulonglong2 hv = h4[q + 4 * k];   // contiguous across q lanes
            ar0 = fma2(wr[2 * k],     hv.x, ar0);
            ar1 = fma2(wr[2 * k + 1], hv.y, ar1);
            az0 = fma2(wz[2 * k],     hv.x, az0);
            az1 = fma2(wz[2 * k + 1], hv.y, az1);
            an0 = fma2(wn[2 * k],     hv.x, an0);
            an1 = fma2(wn[2 * k + 1], hv.y, an1);
        }
        float dr = hsum2(ar0, ar1);
        float dz = hsum2(az0, az1);
        float dn = hsum2(an0, an1);
        // combine the 4 quarter-sums (butterfly leaves full sum in all lanes)
        dr += __shfl_xor_sync(0xffffffffu, dr, 1);
        dz += __shfl_xor_sync(0xffffffffu, dz, 1);
        dn += __shfl_xor_sync(0xffffffffu, dn, 1);
        dr += __shfl_xor_sync(0xffffffffu, dr, 2);
        dz += __shfl_xor_sync(0xffffffffu, dz, 2);
        dn += __shfl_xor_sync(0xffffffffu, dn, 2);

        const float r = sigmoid_fast(fmaf(x, wih_r, br) + dr);
        const float z = sigmoid_fast(fmaf(x, wih_z, bz) + dz);
        const float n = tanh_fast(fmaf(x, wih_n, bin) + r * (dn + bhn));
        const float hnew = fmaf(z, hcur - n, n);   // (1-z)*n + z*h
        hcur = hnew;

        if (q == 0) {
            h_sh[(t + 1) & 1][unit] = hnew;
            // shared ring: backward dir stores reversed so each buffer is an
            // ascending-contiguous global chunk.
            const int slot = dir ? (31 - (t & 31)) : (t & 31);
            ring[(t >> 5) & 1][slot][unit] = hnew;
        }
        // Buffer-reuse guard: ensure the copy issued 16 steps ago has finished
        // READING before anyone (post-barrier) overwrites that buffer.
        if ((t & 31) == 16 && tid == 0)
            asm volatile("cp.async.bulk.wait_group.read 1;" ::: "memory");
        __syncthreads();   // h_new + ring visible; orders the wait above

        if ((t & 31) == 31 && tid == 0) {
            const int buf = (t >> 5) & 1;
            float* dst = dir ? (hout + (T_LEN - 1 - t) * H)
                             : (hout + (t - 31) * H);
            unsigned s = (unsigned)__cvta_generic_to_shared(&ring[buf][0][0]);
            asm volatile("fence.proxy.async.shared::cta;" ::: "memory");
            asm volatile(
                "cp.async.bulk.global.shared::cta.bulk_group [%0], [%1], %2;"
                :: "l"(dst), "r"(s), "r"(32 * H * 4) : "memory");
            asm volatile("cp.async.bulk.commit_group;" ::: "memory");
        }
    }

    // all bulk copies must complete before CTA exit
    if (tid == 0)
        asm volatile("cp.async.bulk.wait_group 0;" ::: "memory");
    __syncthreads();
}

// ---------------------------------------------------------------------------
// probs kernel: one warp per timestep. probs -> out[0:T], kept zeroed.
// ---------------------------------------------------------------------------
__global__ void probs_kernel(const float* __restrict__ w_out,
                             const float* __restrict__ b_out,
                             float* __restrict__ out)
{
    const int warp = threadIdx.x >> 5;
    const int lane = threadIdx.x & 31;
    const int t = blockIdx.x * 8 + warp;
    if (t >= T_LEN) return;

    const float* __restrict__ hf = g_hf + t * H;
    const float* __restrict__ hb = g_hb + t * H;
    float s = 0.0f;
    #pragma unroll
    for (int m = 0; m < 4; m++) {
        const int c = lane + 32 * m;
        s = fmaf(hf[c], w_out[c], s);
        s = fmaf(hb[c], w_out[H + c], s);
    }
    #pragma unroll
    for (int o = 16; o > 0; o >>= 1)
        s += __shfl_down_sync(0xffffffffu, s, o);
    if (lane == 0) {
        const float p = rcpa(1.0f + ex2a(-(s + b_out[0]) * LOG2E));
        out[t]         = p;
        out[T_LEN + t] = 0.0f;   // init kept
    }
}

// ---------------------------------------------------------------------------
// mask kernel: probs > 0.5 bitmap via ballot.
// ---------------------------------------------------------------------------
__global__ void mask_kernel(const float* __restrict__ probs)
{
    const int t = blockIdx.x * blockDim.x + threadIdx.x;
    const unsigned b = __ballot_sync(0xffffffffu, probs[t] > 0.5f);
    if ((t & 31) == 0) g_maskw[t >> 5] = b;
}

// ---------------------------------------------------------------------------
// NMS: window starts via bitmap chase (thread 0, ~1.6k dependent steps),
// then warp-parallel argmax per window.
// ---------------------------------------------------------------------------
__global__ void nms_kernel(const float* __restrict__ probs,
                           float* __restrict__ kept)
{
    __shared__ unsigned words[T_LEN / 32];
    __shared__ int starts[1700];
    __shared__ int nwin_sh;

    const int tid = threadIdx.x;
    for (int k = tid; k < T_LEN / 32; k += blockDim.x) words[k] = g_maskw[k];
    __syncthreads();

    if (tid == 0) {
        int nw = 0;
        int pos = 0;
        while (pos < T_LEN) {
            int wi = pos >> 5;
            unsigned w = words[wi] & (0xffffffffu << (pos & 31));
            while (w == 0) {
                wi++;
                if (wi >= T_LEN / 32) break;
                w = words[wi];
            }
            if (w == 0) break;
            const int s = (wi << 5) + __ffs(w) - 1;
            starts[nw++] = s;
            pos = s + 40;   // MIN_DISTANCE
        }
        nwin_sh = nw;
    }
    __syncthreads();

    const int nwin = nwin_sh;
    const int warp = tid >> 5;
    const int lane = tid & 31;
    for (int wdx = warp; wdx < nwin; wdx += 32) {
        const int s = starts[wdx];
        float bp = -1e30f;
        int   bi = 0x7fffffff;
        #pragma unroll
        for (int off = 0; off < 2; off++) {
            const int tt = s + lane + 32 * off;
            if (lane + 32 * off < 40 && tt < T_LEN) {
                const float p = probs[tt];
                if (p > 0.5f && (p > bp || (p == bp && tt < bi))) {
                    bp = p; bi = tt;
                }
            }
        }
        #pragma unroll
        for (int o = 16; o > 0; o >>= 1) {
            const float op = __shfl_xor_sync(0xffffffffu, bp, o);
            const int   oi = __shfl_xor_sync(0xffffffffu, bi, o);
            if (op > bp || (op == bp && oi < bi)) { bp = op; bi = oi; }
        }
        if (lane == 0) kept[bi] = 1.0f;
    }
}

// ---------------------------------------------------------------------------
extern "C" void kernel_launch(void* const* d_in, const int* in_sizes, int n_in,
                              void* d_out, int out_size)
{
    const float* signal = (const float*)d_in[0];
    const float* Wih_f  = (const float*)d_in[1];
    const float* Whh_f  = (const float*)d_in[2];
    const float* bih_f  = (const float*)d_in[3];
    const float* bhh_f  = (const float*)d_in[4];
    const float* Wih_b  = (const float*)d_in[5];
    const float* Whh_b  = (const float*)d_in[6];
    const float* bih_b  = (const float*)d_in[7];
    const float* bhh_b  = (const float*)d_in[8];
    const float* w_out  = (const float*)d_in[9];
    const float* b_out  = (const float*)d_in[10];
    float* out = (float*)d_out;

    gru_kernel<<<2, 512>>>(signal, Wih_f, Whh_f, bih_f, bhh_f,
                           Wih_b, Whh_b, bih_b, bhh_b);
    probs_kernel<<<T_LEN / 8, 256>>>(w_out, b_out, out);
    mask_kernel<<<T_LEN / 1024, 1024>>>(out);
    nms_kernel<<<1, 1024>>>(out, out + T_LEN);
}

// round 6
// speedup vs baseline: 1.0982x; 1.0982x over previous
#include <cuda_runtime.h>

#define T_LEN 65536
#define H     128

// Scratch: per-timestep hidden states for both directions.
__device__ float g_hf[T_LEN * H];
__device__ float g_hb[T_LEN * H];
__device__ unsigned g_maskw[T_LEN / 32];

// Fast approx math (MUFU only, no IEEE div sequences).
__device__ __forceinline__ float ex2a(float x) {
    float y; asm("ex2.approx.f32 %0, %1;" : "=f"(y) : "f"(x)); return y;
}
__device__ __forceinline__ float rcpa(float x) {
    float y; asm("rcp.approx.f32 %0, %1;" : "=f"(y) : "f"(x)); return y;
}
__device__ __forceinline__ float tanha(float x) {
    float y; asm("tanh.approx.f32 %0, %1;" : "=f"(y) : "f"(x)); return y;
}
#define LOG2E 1.4426950408889634f
// Sigmoid via single-MUFU tanh.approx (used for r,z gates only).
__device__ __forceinline__ float sigmoid_t(float x) {
    return fmaf(0.5f, tanha(0.5f * x), 0.5f);
}
// Accurate-ish tanh (2 MUFU) for the n gate (direct h contributor).
__device__ __forceinline__ float tanh_fast(float x) {
    float ax = fabsf(x);
    float e  = ex2a(ax * (-2.0f * LOG2E));
    float t  = (1.0f - e) * rcpa(1.0f + e);
    return copysignf(t, x);
}
__device__ __forceinline__ float sigmoid_fast(float x) {
    return rcpa(1.0f + ex2a(-x * LOG2E));
}

// Packed f32x2 FMA (2 MACs/instr) — only reachable via inline PTX on sm_103a.
__device__ __forceinline__ unsigned long long fma2(unsigned long long a,
                                                   unsigned long long b,
                                                   unsigned long long c) {
    unsigned long long d;
    asm("fma.rn.f32x2 %0, %1, %2, %3;" : "=l"(d) : "l"(a), "l"(b), "l"(c));
    return d;
}
__device__ __forceinline__ float hsum2(unsigned long long a, unsigned long long b) {
    unsigned long long s;
    asm("add.rn.f32x2 %0, %1, %2;" : "=l"(s) : "l"(a), "l"(b));
    float2 f = *reinterpret_cast<float2*>(&s);
    return f.x + f.y;
}

// ---------------------------------------------------------------------------
// GRU kernel: grid = 2 (dir), 256 threads = 128 unit-pairs.
// Thread (unit, half) owns the 64-col `half` slice of gate rows r,z,n of
// `unit` (96 u64 weight regs). Single shfl_xor(1) combines the halves.
// Async-proxy store ring (bar.sync does NOT drain cp.async.bulk);
// ring STS happens AFTER the barrier (overlaps next step's dot).
// ---------------------------------------------------------------------------
__global__ void __launch_bounds__(256, 1) gru_kernel(
    const float* __restrict__ signal,
    const float* __restrict__ Wih_f, const float* __restrict__ Whh_f,
    const float* __restrict__ bih_f, const float* __restrict__ bhh_f,
    const float* __restrict__ Wih_b, const float* __restrict__ Whh_b,
    const float* __restrict__ bih_b, const float* __restrict__ bhh_b)
{
    const int dir = blockIdx.x;
    const float* __restrict__ Wih = dir ? Wih_b : Wih_f;
    const float* __restrict__ Whh = dir ? Whh_b : Whh_f;
    const float* __restrict__ bih = dir ? bih_b : bih_f;
    const float* __restrict__ bhh = dir ? bhh_b : bhh_f;
    float* __restrict__ hout = dir ? g_hb : g_hf;

    const int tid  = threadIdx.x;
    const int unit = tid >> 1;   // 0..127
    const int half = tid & 1;    // 0..1
    const int col0 = half << 6;  // 0 or 64

    __shared__ __align__(16) float h_sh[2][H];
    __shared__ __align__(16) float ring[2][32][H];   // 32 KB
    __shared__ float sig_sh[2048];                    // 8 KB

    const int row_r = unit;
    const int row_z = H + unit;
    const int row_n = 2 * H + unit;

    // Register-resident recurrent weights: 3 half-rows per thread.
    unsigned long long wr[32], wz[32], wn[32];
    {
        const unsigned long long* pr =
            reinterpret_cast<const unsigned long long*>(Whh + row_r * H + col0);
        const unsigned long long* pz =
            reinterpret_cast<const unsigned long long*>(Whh + row_z * H + col0);
        const unsigned long long* pn =
            reinterpret_cast<const unsigned long long*>(Whh + row_n * H + col0);
        #pragma unroll
        for (int k = 0; k < 32; k++) { wr[k] = pr[k]; wz[k] = pz[k]; wn[k] = pn[k]; }
    }
    const float wih_r = Wih[row_r], wih_z = Wih[row_z], wih_n = Wih[row_n];
    const float br  = bih[row_r] + bhh[row_r];
    const float bz  = bih[row_z] + bhh[row_z];
    const float bin = bih[row_n];
    const float bhn = bhh[row_n];

    float hcur = 0.0f;
    if (tid < H) h_sh[0][tid] = 0.0f;
    __syncthreads();

    for (int t = 0; t < T_LEN; t++) {
        if ((t & 2047) == 0) {
            // previous step ended with __syncthreads -> safe to refill
            for (int k = tid; k < 2048; k += 256) {
                const int idx = t + k;
                sig_sh[k] = dir ? signal[T_LEN - 1 - idx] : signal[idx];
            }
            __syncthreads();
        }
        // Flush the buffer completed over steps [t-32, t-1]: its STS were all
        // drained by earlier barriers; fence makes them async-proxy visible.
        if ((t & 31) == 0 && t > 0 && tid == 0) {
            const int buf = ((t >> 5) + 1) & 1;    // previous buffer
            float* dst = dir ? (hout + (T_LEN - t) * H)       // steps t-32..t-1
                             : (hout + (t - 32) * H);
            unsigned s = (unsigned)__cvta_generic_to_shared(&ring[buf][0][0]);
            asm volatile("fence.proxy.async.shared::cta;" ::: "memory");
            asm volatile(
                "cp.async.bulk.global.shared::cta.bulk_group [%0], [%1], %2;"
                :: "l"(dst), "r"(s), "r"(32 * H * 4) : "memory");
            asm volatile("cp.async.bulk.commit_group;" ::: "memory");
        }
        // Reuse guard: copy issued ~16 steps ago must be done READING.
        if ((t & 31) == 16 && tid == 0)
            asm volatile("cp.async.bulk.wait_group.read 1;" ::: "memory");

        const float x = sig_sh[t & 2047];

        const ulonglong2* h4 =
            reinterpret_cast<const ulonglong2*>(&h_sh[t & 1][col0]);
        unsigned long long ar0 = 0ULL, ar1 = 0ULL;
        unsigned long long az0 = 0ULL, az1 = 0ULL;
        unsigned long long an0 = 0ULL, an1 = 0ULL;
        #pragma unroll
        for (int c = 0; c < 16; c++) {
            const ulonglong2 hv = h4[c];
            ar0 = fma2(wr[2 * c],     hv.x, ar0);
            ar1 = fma2(wr[2 * c + 1], hv.y, ar1);
            az0 = fma2(wz[2 * c],     hv.x, az0);
            az1 = fma2(wz[2 * c + 1], hv.y, az1);
            an0 = fma2(wn[2 * c],     hv.x, an0);
            an1 = fma2(wn[2 * c + 1], hv.y, an1);
        }
        float dr = hsum2(ar0, ar1);
        float dn = hsum2(an0, an1);
        float dz = hsum2(az0, az1);
        // pair-combine halves; order so the r-chain starts earliest
        dr += __shfl_xor_sync(0xffffffffu, dr, 1);
        dn += __shfl_xor_sync(0xffffffffu, dn, 1);
        dz += __shfl_xor_sync(0xffffffffu, dz, 1);

        const float r = sigmoid_t(fmaf(x, wih_r, br) + dr);
        const float n = tanh_fast(fmaf(x, wih_n, bin) + r * (dn + bhn));
        const float z = sigmoid_t(fmaf(x, wih_z, bz) + dz);
        const float hnew = fmaf(z, hcur - n, n);   // (1-z)*n + z*h
        hcur = hnew;

        if (half == 0) h_sh[(t + 1) & 1][unit] = hnew;
        __syncthreads();   // h_new visible; fences WAR on h_sh read

        // Ring store AFTER the barrier: overlaps next step's dot; consumed by
        // the flush 32 steps later (ordered by the intervening barriers).
        if (half == 0) {
            const int slot = dir ? (31 - (t & 31)) : (t & 31);
            ring[(t >> 5) & 1][slot][unit] = hnew;
        }
    }

    // Final buffer (steps T-32..T-1): order its STS, flush, and drain.
    __syncthreads();
    if (tid == 0) {
        const int buf = ((T_LEN >> 5) + 1) & 1;   // buffer of last 32 steps
        float* dst = dir ? hout : (hout + (T_LEN - 32) * H);
        unsigned s = (unsigned)__cvta_generic_to_shared(&ring[buf][0][0]);
        asm volatile("fence.proxy.async.shared::cta;" ::: "memory");
        asm volatile(
            "cp.async.bulk.global.shared::cta.bulk_group [%0], [%1], %2;"
            :: "l"(dst), "r"(s), "r"(32 * H * 4) : "memory");
        asm volatile("cp.async.bulk.commit_group;" ::: "memory");
        asm volatile("cp.async.bulk.wait_group 0;" ::: "memory");
    }
    __syncthreads();
}

// ---------------------------------------------------------------------------
// probs kernel: one warp per timestep. probs -> out[0:T], kept zeroed.
// ---------------------------------------------------------------------------
__global__ void probs_kernel(const float* __restrict__ w_out,
                             const float* __restrict__ b_out,
                             float* __restrict__ out)
{
    const int warp = threadIdx.x >> 5;
    const int lane = threadIdx.x & 31;
    const int t = blockIdx.x * 8 + warp;
    if (t >= T_LEN) return;

    const float* __restrict__ hf = g_hf + t * H;
    const float* __restrict__ hb = g_hb + t * H;
    float s = 0.0f;
    #pragma unroll
    for (int m = 0; m < 4; m++) {
        const int c = lane + 32 * m;
        s = fmaf(hf[c], w_out[c], s);
        s = fmaf(hb[c], w_out[H + c], s);
    }
    #pragma unroll
    for (int o = 16; o > 0; o >>= 1)
        s += __shfl_down_sync(0xffffffffu, s, o);
    if (lane == 0) {
        const float p = sigmoid_fast(s + b_out[0]);
        out[t]         = p;
        out[T_LEN + t] = 0.0f;   // init kept
    }
}

// ---------------------------------------------------------------------------
// mask kernel: probs > 0.5 bitmap via ballot.
// ---------------------------------------------------------------------------
__global__ void mask_kernel(const float* __restrict__ probs)
{
    const int t = blockIdx.x * blockDim.x + threadIdx.x;
    const unsigned b = __ballot_sync(0xffffffffu, probs[t] > 0.5f);
    if ((t & 31) == 0) g_maskw[t >> 5] = b;
}

// ---------------------------------------------------------------------------
// NMS: window starts via bitmap chase (thread 0, ~1.6k dependent steps),
// then warp-parallel argmax per window.
// ---------------------------------------------------------------------------
__global__ void nms_kernel(const float* __restrict__ probs,
                           float* __restrict__ kept)
{
    __shared__ unsigned words[T_LEN / 32];
    __shared__ int starts[1700];
    __shared__ int nwin_sh;

    const int tid = threadIdx.x;
    for (int k = tid; k < T_LEN / 32; k += blockDim.x) words[k] = g_maskw[k];
    __syncthreads();

    if (tid == 0) {
        int nw = 0;
        int pos = 0;
        while (pos < T_LEN) {
            int wi = pos >> 5;
            unsigned w = words[wi] & (0xffffffffu << (pos & 31));
            while (w == 0) {
                wi++;
                if (wi >= T_LEN / 32) break;
                w = words[wi];
            }
            if (w == 0) break;
            const int s = (wi << 5) + __ffs(w) - 1;
            starts[nw++] = s;
            pos = s + 40;   // MIN_DISTANCE
        }
        nwin_sh = nw;
    }
    __syncthreads();

    const int nwin = nwin_sh;
    const int warp = tid >> 5;
    const int lane = tid & 31;
    for (int wdx = warp; wdx < nwin; wdx += 32) {
        const int s = starts[wdx];
        float bp = -1e30f;
        int   bi = 0x7fffffff;
        #pragma unroll
        for (int off = 0; off < 2; off++) {
            const int tt = s + lane + 32 * off;
            if (lane + 32 * off < 40 && tt < T_LEN) {
                const float p = probs[tt];
                if (p > 0.5f && (p > bp || (p == bp && tt < bi))) {
                    bp = p; bi = tt;
                }
            }
        }
        #pragma unroll
        for (int o = 16; o > 0; o >>= 1) {
            const float op = __shfl_xor_sync(0xffffffffu, bp, o);
            const int   oi = __shfl_xor_sync(0xffffffffu, bi, o);
            if (op > bp || (op == bp && oi < bi)) { bp = op; bi = oi; }
        }
        if (lane == 0) kept[bi] = 1.0f;
    }
}

// ---------------------------------------------------------------------------
extern "C" void kernel_launch(void* const* d_in, const int* in_sizes, int n_in,
                              void* d_out, int out_size)
{
    const float* signal = (const float*)d_in[0];
    const float* Wih_f  = (const float*)d_in[1];
    const float* Whh_f  = (const float*)d_in[2];
    const float* bih_f  = (const float*)d_in[3];
    const float* bhh_f  = (const float*)d_in[4];
    const float* Wih_b  = (const float*)d_in[5];
    const float* Whh_b  = (const float*)d_in[6];
    const float* bih_b  = (const float*)d_in[7];
    const float* bhh_b  = (const float*)d_in[8];
    const float* w_out  = (const float*)d_in[9];
    const float* b_out  = (const float*)d_in[10];
    float* out = (float*)d_out;

    gru_kernel<<<2, 256>>>(signal, Wih_f, Whh_f, bih_f, bhh_f,
                           Wih_b, Whh_b, bih_b, bhh_b);
    probs_kernel<<<T_LEN / 8, 256>>>(w_out, b_out, out);
    mask_kernel<<<T_LEN / 1024, 1024>>>(out);
    nms_kernel<<<1, 1024>>>(out, out + T_LEN);
}